// round 14
// baseline (speedup 1.0000x reference)
#include <cuda_runtime.h>
#include <math.h>

#define C 10
#define NSTATS 31            // 10 sum_p, 10 sum_p2, 10 sum_x, 1 sum_logS
#define NBLOCKS 1184         // 8 * 148; last-block reduce assumes 8 segs * 148
#define NTHREADS 256
#define NEWTON_ITERS 20

// Per-block partial sums + completion counter (reset each launch by last block)
__device__ float g_partials[NBLOCKS * 32];
__device__ unsigned int g_counter = 0;

// ---------------------------------------------------------------------------
// Fused digamma + trigamma, branch-free 6-step recurrence (valid for x > 0:
// after 6 predicated increments x >= 6, asymptotic series applies).
// ---------------------------------------------------------------------------
__device__ __forceinline__ void psi01(float x, float& d0, float& d1)
{
    float r0 = 0.0f, r1 = 0.0f;
#pragma unroll
    for (int i = 0; i < 6; i++) {
        float inv = __fdividef(1.0f, x);
        bool small = (x < 6.0f);
        r0 = small ? (r0 - inv) : r0;
        r1 = small ? fmaf(inv, inv, r1) : r1;
        x  = small ? (x + 1.0f) : x;
    }
    float inv = __fdividef(1.0f, x);
    float f = inv * inv;
    float s0 = f * (1.0f/12.0f - f * (1.0f/120.0f - f * (1.0f/252.0f - f * (1.0f/240.0f - f * (1.0f/132.0f)))));
    float s1 = (1.0f + 0.5f * inv + f * (1.0f/6.0f - f * (1.0f/30.0f - f * (1.0f/42.0f - f * (1.0f/30.0f))))) * inv;
    d0 = r0 + __logf(x) - 0.5f * inv - s0;
    d1 = r1 + s1;
}

// Dual interleaved butterfly over 16 lanes (components in lanes 0..9,
// lanes 10..15 carry zeros; lanes 16..31 shadow lanes 0..15).
__device__ __forceinline__ void wsum2_16(float& a, float& b)
{
#pragma unroll
    for (int off = 8; off > 0; off >>= 1) {
        float ta = __shfl_xor_sync(0xffffffffu, a, off);
        float tb = __shfl_xor_sync(0xffffffffu, b, off);
        a += ta; b += tb;
    }
}

__device__ __forceinline__ float wsum16(float v)
{
#pragma unroll
    for (int off = 8; off > 0; off >>= 1)
        v += __shfl_xor_sync(0xffffffffu, v, off);
    return v;
}

// ---------------------------------------------------------------------------
// ONE kernel: stream stats, block-reduce partials, last block reduces all
// partials and runs the warp-parallel Newton solve.
// __launch_bounds__(256, 4): cap regs at 64 so 4 blocks/SM stay resident —
// R13 showed the streaming phase lives or dies on occupancy, not prefetch.
// ---------------------------------------------------------------------------
__global__ void __launch_bounds__(NTHREADS, 4)
fused_kernel(const float* __restrict__ x, int n, float* __restrict__ out)
{
    float sp[C];   // sum p
    float sp2[C];  // sum p^2
    float sx[C];   // sum x
    float slog = 0.0f;  // sum log S
#pragma unroll
    for (int j = 0; j < C; j++) { sp[j] = 0.0f; sp2[j] = 0.0f; sx[j] = 0.0f; }

    const int npairs = n >> 1;
    const int stride = NBLOCKS * NTHREADS;
    const float4* bp = reinterpret_cast<const float4*>(x);

    for (int pair = blockIdx.x * NTHREADS + threadIdx.x; pair < npairs; pair += stride) {
        const float4* base = bp + (size_t)pair * 5;
        float4 t0 = __ldg(base + 0);
        float4 t1 = __ldg(base + 1);
        float4 t2 = __ldg(base + 2);
        float4 t3 = __ldg(base + 3);
        float4 t4 = __ldg(base + 4);
        float v[20];
        v[0]=t0.x; v[1]=t0.y; v[2]=t0.z; v[3]=t0.w;
        v[4]=t1.x; v[5]=t1.y; v[6]=t1.z; v[7]=t1.w;
        v[8]=t2.x; v[9]=t2.y; v[10]=t2.z; v[11]=t2.w;
        v[12]=t3.x; v[13]=t3.y; v[14]=t3.z; v[15]=t3.w;
        v[16]=t4.x; v[17]=t4.y; v[18]=t4.z; v[19]=t4.w;

#pragma unroll
        for (int r = 0; r < 2; r++) {
            const float* xr = v + r * C;
            float e[C];
            float S = 0.0f;
#pragma unroll
            for (int j = 0; j < C; j++) { e[j] = __expf(xr[j]); S += e[j]; }
            float rS = __fdividef(1.0f, S);
            slog += __logf(S);
#pragma unroll
            for (int j = 0; j < C; j++) {
                float p = e[j] * rS;
                sp[j]  += p;
                sp2[j]  = fmaf(p, p, sp2[j]);
                sx[j]  += xr[j];
            }
        }
    }

    // Tail row if n is odd
    if ((n & 1) && blockIdx.x == 0 && threadIdx.x == 0) {
        const float* xr = x + (size_t)(n - 1) * C;
        float e[C];
        float S = 0.0f;
#pragma unroll
        for (int j = 0; j < C; j++) { e[j] = __expf(xr[j]); S += e[j]; }
        float rS = __fdividef(1.0f, S);
        slog += __logf(S);
#pragma unroll
        for (int j = 0; j < C; j++) {
            float p = e[j] * rS;
            sp[j]  += p;
            sp2[j]  = fmaf(p, p, sp2[j]);
            sx[j]  += xr[j];
        }
    }

    // ---- block reduction of 31 values ----
#pragma unroll
    for (int off = 16; off > 0; off >>= 1) {
#pragma unroll
        for (int j = 0; j < C; j++) {
            sp[j]  += __shfl_down_sync(0xffffffffu, sp[j],  off);
            sp2[j] += __shfl_down_sync(0xffffffffu, sp2[j], off);
            sx[j]  += __shfl_down_sync(0xffffffffu, sx[j],  off);
        }
        slog += __shfl_down_sync(0xffffffffu, slog, off);
    }

    __shared__ float sm[NTHREADS / 32][NSTATS];
    const int warp = threadIdx.x >> 5;
    const int lane = threadIdx.x & 31;
    if (lane == 0) {
#pragma unroll
        for (int j = 0; j < C; j++) {
            sm[warp][j]        = sp[j];
            sm[warp][C + j]    = sp2[j];
            sm[warp][2*C + j]  = sx[j];
        }
        sm[warp][30] = slog;
    }
    __syncthreads();

    if (threadIdx.x < NSTATS) {
        float s = 0.0f;
#pragma unroll
        for (int w = 0; w < NTHREADS / 32; w++) s += sm[w][threadIdx.x];
        g_partials[(size_t)blockIdx.x * 32 + threadIdx.x] = s;
    }

    // ---- last-block election ----
    __shared__ unsigned int s_last;
    __threadfence();
    if (threadIdx.x == 0) {
        unsigned int prev = atomicAdd(&g_counter, 1u);
        s_last = (prev == NBLOCKS - 1) ? 1u : 0u;
    }
    __syncthreads();
    if (!s_last) return;

    // =========================================================================
    // LAST BLOCK: reduce g_partials (8 segs x 148 blocks), then Newton solve.
    // =========================================================================
    __shared__ double red2[8][32];
    __shared__ double stat[32];
    {
        const int t    = threadIdx.x;
        const int comp = t & 31;
        const int seg  = t >> 5;       // 0..7, 148 blocks each
        double a0 = 0.0, a1 = 0.0, a2 = 0.0, a3 = 0.0;
        const int base = seg * 148;
#pragma unroll
        for (int i = 0; i < 37; i++) {
            const int b = base + i * 4;
            a0 += (double)g_partials[(size_t)(b + 0) * 32 + comp];
            a1 += (double)g_partials[(size_t)(b + 1) * 32 + comp];
            a2 += (double)g_partials[(size_t)(b + 2) * 32 + comp];
            a3 += (double)g_partials[(size_t)(b + 3) * 32 + comp];
        }
        red2[seg][comp] = (a0 + a1) + (a2 + a3);
    }
    __syncthreads();

    if (threadIdx.x < 32) {
        double s = 0.0;
#pragma unroll
        for (int w = 0; w < 8; w++) s += red2[w][threadIdx.x];
        stat[threadIdx.x] = s;
    }
    __syncthreads();

    if (threadIdx.x < 32) {
        const int t = threadIdx.x;
        const int lane16 = t & 15;         // lanes 16..31 mirror 0..15
        const double nn_d = (double)n;
        const float  nn   = (float)n;
        const float  rnn  = __fdividef(1.0f, nn);
        const bool   act  = (lane16 < C);

        float m1 = 0.0f, m2 = 0.0f, lp = 0.0f;
        if (act) {
            m1 = (float)(stat[lane16] / nn_d);
            m2 = (float)(stat[C + lane16] / nn_d);
            lp = (float)((stat[2*C + lane16] - stat[30]) / nn_d);  // mean log p_j
        }

        // method-of-moments init
        float ratio = act ? __fdividef(m1 - m2, m2 - m1 * m1) : 0.0f;
        float cc = wsum16(ratio) * (1.0f / (float)C);
        float a = act ? (m1 * cc) : 0.0f;

#pragma unroll 1
        for (int k = 0; k < NEWTON_ITERS; k++) {
            float sumA = wsum16(act ? a : 0.0f);

            float dgs, tgs, dga, tga;
            psi01(sumA, dgs, tgs);
            psi01(act ? a : 1.0f, dga, tga);

            float g = 0.0f, qi = 0.0f, gq = 0.0f;
            if (act) {
                g  = (dgs - dga + lp) * nn;
                qi = __fdividef(-rnn, tga);          // 1/q, q = -n*psi1(a)
                gq = g * qi;
            }
            float num = gq, sumqi = qi;
            wsum2_16(num, sumqi);

            float den = __fdividef(rnn, tgs) + sumqi;   // 1/z + sum(1/q)
            float bb  = __fdividef(num, den);

            if (act) a -= (g - bb) * qi;
        }
        if (t < C) out[t] = a;
    }

    // reset counter for the next (graph-replayed) launch
    if (threadIdx.x == 0) g_counter = 0;
}

extern "C" void kernel_launch(void* const* d_in, const int* in_sizes, int n_in,
                              void* d_out, int out_size)
{
    const float* x = (const float*)d_in[0];
    const int n = in_sizes[0] / C;      // number of rows
    float* out = (float*)d_out;

    fused_kernel<<<NBLOCKS, NTHREADS>>>(x, n, out);
}

// round 15
// speedup vs baseline: 1.3599x; 1.3599x over previous
#include <cuda_runtime.h>
#include <math.h>

#define C 10
#define NSTATS 31            // 10 sum_p, 10 sum_p2, 10 sum_x, 1 sum_logS
#define NBLOCKS 592          // 4 * 148; last-block reduce assumes 8 segs * 74
#define NTHREADS 256
#define NEWTON_ITERS 20

// Per-block partial sums + completion counter (reset each launch by last block)
__device__ float g_partials[NBLOCKS * 32];
__device__ unsigned int g_counter = 0;

// ---------------------------------------------------------------------------
// Fused digamma + trigamma, branch-free 6-step recurrence (valid for x > 0:
// after 6 predicated increments x >= 6, asymptotic series applies).
// ---------------------------------------------------------------------------
__device__ __forceinline__ void psi01(float x, float& d0, float& d1)
{
    float r0 = 0.0f, r1 = 0.0f;
#pragma unroll
    for (int i = 0; i < 6; i++) {
        float inv = __fdividef(1.0f, x);
        bool small = (x < 6.0f);
        r0 = small ? (r0 - inv) : r0;
        r1 = small ? fmaf(inv, inv, r1) : r1;
        x  = small ? (x + 1.0f) : x;
    }
    float inv = __fdividef(1.0f, x);
    float f = inv * inv;
    float s0 = f * (1.0f/12.0f - f * (1.0f/120.0f - f * (1.0f/252.0f - f * (1.0f/240.0f - f * (1.0f/132.0f)))));
    float s1 = (1.0f + 0.5f * inv + f * (1.0f/6.0f - f * (1.0f/30.0f - f * (1.0f/42.0f - f * (1.0f/30.0f))))) * inv;
    d0 = r0 + __logf(x) - 0.5f * inv - s0;
    d1 = r1 + s1;
}

// Dual interleaved butterfly over 16 lanes (components in lanes 0..9,
// lanes 10..15 carry zeros; lanes 16..31 shadow lanes 0..15).
__device__ __forceinline__ void wsum2_16(float& a, float& b)
{
#pragma unroll
    for (int off = 8; off > 0; off >>= 1) {
        float ta = __shfl_xor_sync(0xffffffffu, a, off);
        float tb = __shfl_xor_sync(0xffffffffu, b, off);
        a += ta; b += tb;
    }
}

__device__ __forceinline__ float wsum16(float v)
{
#pragma unroll
    for (int off = 8; off > 0; off >>= 1)
        v += __shfl_xor_sync(0xffffffffu, v, off);
    return v;
}

// ---------------------------------------------------------------------------
// Last-block tail: reduce g_partials (8 segs x 74 blocks), Newton solve.
// __noinline__ is load-bearing: it isolates this fp64-heavy, once-per-launch
// code in its own ABI frame so ptxas schedules the streaming loop (and its
// front-batched LDG.128s) without this code's register pressure (R14 lesson).
// Called uniformly by all 256 threads of the elected last block.
// ---------------------------------------------------------------------------
__device__ __noinline__ void tail_reduce_solve(float* __restrict__ out, int n)
{
    __shared__ double red2[8][32];
    __shared__ double stat[32];
    {
        const int t    = threadIdx.x;
        const int comp = t & 31;
        const int seg  = t >> 5;       // 0..7, 74 blocks each
        double a0 = 0.0, a1 = 0.0, a2 = 0.0, a3 = 0.0;
        const int base = seg * 74;
#pragma unroll
        for (int i = 0; i < 18; i++) {
            const int b = base + i * 4;
            a0 += (double)g_partials[(size_t)(b + 0) * 32 + comp];
            a1 += (double)g_partials[(size_t)(b + 1) * 32 + comp];
            a2 += (double)g_partials[(size_t)(b + 2) * 32 + comp];
            a3 += (double)g_partials[(size_t)(b + 3) * 32 + comp];
        }
        a0 += (double)g_partials[(size_t)(base + 72) * 32 + comp];
        a1 += (double)g_partials[(size_t)(base + 73) * 32 + comp];
        red2[seg][comp] = (a0 + a1) + (a2 + a3);
    }
    __syncthreads();

    if (threadIdx.x < 32) {
        double s = 0.0;
#pragma unroll
        for (int w = 0; w < 8; w++) s += red2[w][threadIdx.x];
        stat[threadIdx.x] = s;
    }
    __syncthreads();

    if (threadIdx.x < 32) {
        const int t = threadIdx.x;
        const int lane16 = t & 15;         // lanes 16..31 mirror 0..15
        const double nn_d = (double)n;
        const float  nn   = (float)n;
        const float  rnn  = __fdividef(1.0f, nn);
        const bool   act  = (lane16 < C);

        float m1 = 0.0f, m2 = 0.0f, lp = 0.0f;
        if (act) {
            m1 = (float)(stat[lane16] / nn_d);
            m2 = (float)(stat[C + lane16] / nn_d);
            lp = (float)((stat[2*C + lane16] - stat[30]) / nn_d);  // mean log p_j
        }

        // method-of-moments init
        float ratio = act ? __fdividef(m1 - m2, m2 - m1 * m1) : 0.0f;
        float cc = wsum16(ratio) * (1.0f / (float)C);
        float a = act ? (m1 * cc) : 0.0f;

#pragma unroll 1
        for (int k = 0; k < NEWTON_ITERS; k++) {
            float sumA = wsum16(act ? a : 0.0f);

            float dgs, tgs, dga, tga;
            psi01(sumA, dgs, tgs);
            psi01(act ? a : 1.0f, dga, tga);

            float g = 0.0f, qi = 0.0f, gq = 0.0f;
            if (act) {
                g  = (dgs - dga + lp) * nn;
                qi = __fdividef(-rnn, tga);          // 1/q, q = -n*psi1(a)
                gq = g * qi;
            }
            float num = gq, sumqi = qi;
            wsum2_16(num, sumqi);

            float den = __fdividef(rnn, tgs) + sumqi;   // 1/z + sum(1/q)
            float bb  = __fdividef(num, den);

            if (act) a -= (g - bb) * qi;
        }
        if (t < C) out[t] = a;
    }

    // reset counter for the next (graph-replayed) launch
    if (threadIdx.x == 0) g_counter = 0;
}

// ---------------------------------------------------------------------------
// ONE kernel: stream stats, block-reduce partials, elected last block calls
// the __noinline__ tail. No min-blocks cap (R14 lesson: the cap re-scheduled
// the loop and destroyed load batching).
// ---------------------------------------------------------------------------
__global__ void __launch_bounds__(NTHREADS)
fused_kernel(const float* __restrict__ x, int n, float* __restrict__ out)
{
    float sp[C];   // sum p
    float sp2[C];  // sum p^2
    float sx[C];   // sum x
    float slog = 0.0f;  // sum log S
#pragma unroll
    for (int j = 0; j < C; j++) { sp[j] = 0.0f; sp2[j] = 0.0f; sx[j] = 0.0f; }

    const int npairs = n >> 1;
    const int stride = NBLOCKS * NTHREADS;
    const float4* bp = reinterpret_cast<const float4*>(x);

    for (int pair = blockIdx.x * NTHREADS + threadIdx.x; pair < npairs; pair += stride) {
        const float4* base = bp + (size_t)pair * 5;
        float4 t0 = __ldg(base + 0);
        float4 t1 = __ldg(base + 1);
        float4 t2 = __ldg(base + 2);
        float4 t3 = __ldg(base + 3);
        float4 t4 = __ldg(base + 4);
        float v[20];
        v[0]=t0.x; v[1]=t0.y; v[2]=t0.z; v[3]=t0.w;
        v[4]=t1.x; v[5]=t1.y; v[6]=t1.z; v[7]=t1.w;
        v[8]=t2.x; v[9]=t2.y; v[10]=t2.z; v[11]=t2.w;
        v[12]=t3.x; v[13]=t3.y; v[14]=t3.z; v[15]=t3.w;
        v[16]=t4.x; v[17]=t4.y; v[18]=t4.z; v[19]=t4.w;

#pragma unroll
        for (int r = 0; r < 2; r++) {
            const float* xr = v + r * C;
            float e[C];
            float S = 0.0f;
#pragma unroll
            for (int j = 0; j < C; j++) { e[j] = __expf(xr[j]); S += e[j]; }
            float rS = __fdividef(1.0f, S);
            slog += __logf(S);
#pragma unroll
            for (int j = 0; j < C; j++) {
                float p = e[j] * rS;
                sp[j]  += p;
                sp2[j]  = fmaf(p, p, sp2[j]);
                sx[j]  += xr[j];
            }
        }
    }

    // Tail row if n is odd
    if ((n & 1) && blockIdx.x == 0 && threadIdx.x == 0) {
        const float* xr = x + (size_t)(n - 1) * C;
        float e[C];
        float S = 0.0f;
#pragma unroll
        for (int j = 0; j < C; j++) { e[j] = __expf(xr[j]); S += e[j]; }
        float rS = __fdividef(1.0f, S);
        slog += __logf(S);
#pragma unroll
        for (int j = 0; j < C; j++) {
            float p = e[j] * rS;
            sp[j]  += p;
            sp2[j]  = fmaf(p, p, sp2[j]);
            sx[j]  += xr[j];
        }
    }

    // ---- block reduction of 31 values ----
#pragma unroll
    for (int off = 16; off > 0; off >>= 1) {
#pragma unroll
        for (int j = 0; j < C; j++) {
            sp[j]  += __shfl_down_sync(0xffffffffu, sp[j],  off);
            sp2[j] += __shfl_down_sync(0xffffffffu, sp2[j], off);
            sx[j]  += __shfl_down_sync(0xffffffffu, sx[j],  off);
        }
        slog += __shfl_down_sync(0xffffffffu, slog, off);
    }

    __shared__ float sm[NTHREADS / 32][NSTATS];
    const int warp = threadIdx.x >> 5;
    const int lane = threadIdx.x & 31;
    if (lane == 0) {
#pragma unroll
        for (int j = 0; j < C; j++) {
            sm[warp][j]        = sp[j];
            sm[warp][C + j]    = sp2[j];
            sm[warp][2*C + j]  = sx[j];
        }
        sm[warp][30] = slog;
    }
    __syncthreads();

    if (threadIdx.x < NSTATS) {
        float s = 0.0f;
#pragma unroll
        for (int w = 0; w < NTHREADS / 32; w++) s += sm[w][threadIdx.x];
        g_partials[(size_t)blockIdx.x * 32 + threadIdx.x] = s;
    }

    // ---- last-block election ----
    __shared__ unsigned int s_last;
    __threadfence();
    if (threadIdx.x == 0) {
        unsigned int prev = atomicAdd(&g_counter, 1u);
        s_last = (prev == NBLOCKS - 1) ? 1u : 0u;
    }
    __syncthreads();
    if (!s_last) return;

    tail_reduce_solve(out, n);
}

extern "C" void kernel_launch(void* const* d_in, const int* in_sizes, int n_in,
                              void* d_out, int out_size)
{
    const float* x = (const float*)d_in[0];
    const int n = in_sizes[0] / C;      // number of rows
    float* out = (float*)d_out;

    fused_kernel<<<NBLOCKS, NTHREADS>>>(x, n, out);
}